// round 7
// baseline (speedup 1.0000x reference)
#include <cuda_runtime.h>
#include <math.h>

#define PS 32
#define NB 36
#define WPB 8
#define THREADS (WPB * 32)
#define NCOPY 16

typedef unsigned long long u64p;

__device__ __forceinline__ u64p pk(float lo, float hi) {
    u64p r; asm("mov.b64 %0, {%1, %2};" : "=l"(r) : "f"(lo), "f"(hi)); return r;
}
__device__ __forceinline__ void upk(u64p v, float& lo, float& hi) {
    asm("mov.b64 {%0, %1}, %2;" : "=f"(lo), "=f"(hi) : "l"(v));
}
__device__ __forceinline__ u64p add2(u64p a, u64p b) {
    u64p r; asm("add.rn.f32x2 %0, %1, %2;" : "=l"(r) : "l"(a), "l"(b)); return r;
}
__device__ __forceinline__ u64p mul2(u64p a, u64p b) {
    u64p r; asm("mul.rn.f32x2 %0, %1, %2;" : "=l"(r) : "l"(a), "l"(b)); return r;
}
__device__ __forceinline__ u64p fma2(u64p a, u64p b, u64p c) {
    u64p r; asm("fma.rn.f32x2 %0, %1, %2, %3;" : "=l"(r) : "l"(a), "l"(b), "l"(c)); return r;
}

#define PKC(v) ((((u64p)__float_as_uint(v)) << 32) | (u64p)__float_as_uint(v))

__global__ __launch_bounds__(THREADS, 8)
void orient_kernel(const float* __restrict__ x,
                   const float* __restrict__ gk,
                   float* __restrict__ out,
                   int B)
{
    __shared__ float s_gk[PS * PS];
    __shared__ float s_priv[WPB][NB * NCOPY];
    __shared__ float s_hist[WPB][40];
    __shared__ float s_sm[WPB][40];

    const int tid   = threadIdx.x;
    const int w     = tid >> 5;
    const int lane  = tid & 31;
    const int patch = blockIdx.x * WPB + w;
    const bool valid = (patch < B);

    for (int i = tid; i < PS * PS; i += THREADS) s_gk[i] = gk[i];

    float* priv = s_priv[w];
    #pragma unroll
    for (int i = lane; i < NB * NCOPY; i += 32) priv[i] = 0.0f;
    __syncthreads();

    const float PI_F  = 3.14159265358979323846f;
    const float TPI_F = 6.28318530717958647692f;
    const unsigned FULL = 0xffffffffu;

    const u64p HALF2 = PKC(0.5f);
    const u64p NEG12 = PKC(-1.0f);
    const u64p PI2   = PKC(PI_F);
    const u64p C362  = PKC(36.0f);
    const u64p EPS2  = PKC(1e-10f);
    const u64p ONE2  = PKC(1.0f);

    const int h    = lane >> 4;        // row-half
    const int hl   = lane & 15;        // column-pair index
    const int col0 = 2 * hl;

    const float* xp = x + (size_t)(valid ? patch : 0) * (PS * PS);
    const float* xh = xp + h * 16 * PS;
    const int gkb   = h * 16 * PS + col0;

    float2 cur = *(const float2*)(xh + col0);
    float2 prv = (h == 0) ? cur : *(const float2*)(xh - PS + col0);
    float2 nxt = *(const float2*)(xh + PS + col0);

    #pragma unroll
    for (int r = 0; r < 16; r++) {
        float Lup = __shfl_up_sync(FULL, cur.y, 1, 16);
        float Rdn = __shfl_down_sync(FULL, cur.x, 1, 16);
        float left0  = (hl == 0)  ? cur.x : Lup;
        float right1 = (hl == 15) ? cur.y : Rdn;

        // FROZEN gradients, packed (fma(-1,b,a) == fsub bitwise)
        u64p prv2 = pk(prv.x, prv.y);
        u64p nxt2 = pk(nxt.x, nxt.y);
        u64p gy2  = mul2(fma2(nxt2, NEG12, prv2), HALF2);   // 0.5*(prv-nxt)
        u64p ga   = pk(left0, cur.x);
        u64p gb   = pk(cur.y, right1);
        u64p gx2  = mul2(fma2(gb, NEG12, ga), HALF2);       // 0.5*(left-right)

        float gx0, gx1, gy0, gy1;
        upk(gx2, gx0, gx1);
        upk(gy2, gy0, gy1);

        // FROZEN: libdevice atan2f (bit-exact vs XLA)
        float ori0 = atan2f(gy0, gx0);
        float ori1 = atan2f(gy1, gx1);

        // FROZEN chain: rn(36 * rn(ori+pi)) packed, scalar IEEE div
        u64p t36 = mul2(add2(pk(ori0, ori1), PI2), C362);
        float ta, tb; upk(t36, ta, tb);
        float obig0 = __fdiv_rn(ta, TPI_F);
        float obig1 = __fdiv_rn(tb, TPI_F);
        // trunc == floor (obig >= 0); (float)bx == floorf(obig) exactly
        int bxr = __float2int_rz(obig0);
        int byr = __float2int_rz(obig1);
        float bo00 = (float)bxr;
        float bo01 = (float)byr;
        int bx = (bxr >= NB) ? bxr - NB : bxr;
        int by = (byr >= NB) ? byr - NB : byr;

        // continuous path (re-roundable): wo1, mag, wv
        u64p wo2  = fma2(pk(bo00, bo01), NEG12, pk(obig0, obig1)); // obig-bo0
        u64p m2v  = fma2(gx2, gx2, fma2(gy2, gy2, EPS2));
        float m20, m21; upk(m2v, m20, m21);
        u64p rs2  = pk(rsqrtf(m20), rsqrtf(m21));
        u64p gk2  = *(const u64p*)(s_gk + gkb + r * PS);           // LDS.64
        u64p mag2 = mul2(mul2(m2v, rs2), gk2);
        u64p wv2  = mul2(fma2(wo2, NEG12, ONE2), mag2);            // (1-wo1)*mag
        float wx, wy; upk(wv2, wx, wy);

        // proven hist: lanes<16 apply own + partner updates sequentially.
        // partner bins packed into one shuffle.
        int   bpk = __shfl_down_sync(FULL, bx | (by << 8), 16);
        float wx2 = __shfl_down_sync(FULL, wx, 16);
        float wy2 = __shfl_down_sync(FULL, wy, 16);
        if (lane < 16) {
            int bx2 = bpk & 255;
            int by2 = bpk >> 8;
            priv[bx  * NCOPY + hl] += wx;
            priv[by  * NCOPY + hl] += wy;
            priv[bx2 * NCOPY + hl] += wx2;
            priv[by2 * NCOPY + hl] += wy2;
        }

        prv = cur;
        cur = nxt;
        if (r < 15) {
            if (r < 14 || h == 0) nxt = *(const float2*)(xh + (r + 2) * PS + col0);
            else                  nxt = cur;     // replicate last row
        }
    }
    __syncwarp();

    // reduce 16 copies -> 36 bins (conflict-free rotation)
    const int rot = lane >> 1;
    float s1 = 0.0f;
    #pragma unroll
    for (int c = 0; c < NCOPY; c++) {
        int cc = (c + rot) & 15;
        s1 += priv[lane * NCOPY + cc];
    }
    const int l2 = 32 + (lane & 3);
    float s2 = 0.0f;
    #pragma unroll
    for (int c = 0; c < NCOPY; c++) {
        int cc = (c + rot) & 15;
        s2 += priv[l2 * NCOPY + cc];
    }
    s_hist[w][lane] = s1;
    if (lane < 4) s_hist[w][32 + lane] = s2;
    __syncwarp();

    // zero-padded smoothing [0.33, 0.34, 0.33]
    {
        float h0 = s_hist[w][lane];
        float hm = (lane > 0) ? s_hist[w][lane - 1] : 0.0f;
        float hp = s_hist[w][lane + 1];
        float a  = __fmul_rn(0.33f, hm);
        float bb = __fmul_rn(0.34f, h0);
        float c  = __fmul_rn(0.33f, hp);
        s_sm[w][lane] = __fadd_rn(__fadd_rn(a, bb), c);
    }
    if (lane < 4) {
        int i = 32 + lane;
        float h0 = s_hist[w][i];
        float hm = s_hist[w][i - 1];
        float hp = (i < NB - 1) ? s_hist[w][i + 1] : 0.0f;
        float a  = __fmul_rn(0.33f, hm);
        float bb = __fmul_rn(0.34f, h0);
        float c  = __fmul_rn(0.33f, hp);
        s_sm[w][i] = __fadd_rn(__fadd_rn(a, bb), c);
    }
    __syncwarp();

    if (lane == 0 && valid) {
        float best = s_sm[w][0];
        int   bi   = 0;
        #pragma unroll
        for (int i = 1; i < NB; i++) {
            float v = s_sm[w][i];
            if (v > best) { best = v; bi = i; }
        }
        float ang = __fsub_rn(__fdiv_rn(__fmul_rn(TPI_F, (float)bi), (float)NB), PI_F);
        out[patch] = -ang;
    }
}

extern "C" void kernel_launch(void* const* d_in, const int* in_sizes, int n_in,
                              void* d_out, int out_size)
{
    const float* x  = (const float*)d_in[0];
    const float* gk = (const float*)d_in[1];
    float* out = (float*)d_out;
    int B = in_sizes[0] / (PS * PS);
    int nblocks = (B + WPB - 1) / WPB;
    orient_kernel<<<nblocks, THREADS>>>(x, gk, out, B);
}

// round 8
// speedup vs baseline: 1.1292x; 1.1292x over previous
#include <cuda_runtime.h>
#include <math.h>

#define PS 32
#define NB 36
#define WPB 8
#define THREADS (WPB * 32)
#define NCOPY 16

typedef unsigned long long u64p;

__device__ __forceinline__ u64p pk(float lo, float hi) {
    u64p r; asm("mov.b64 %0, {%1, %2};" : "=l"(r) : "f"(lo), "f"(hi)); return r;
}
__device__ __forceinline__ void upk(u64p v, float& lo, float& hi) {
    asm("mov.b64 {%0, %1}, %2;" : "=f"(lo), "=f"(hi) : "l"(v));
}
__device__ __forceinline__ u64p add2(u64p a, u64p b) {
    u64p r; asm("add.rn.f32x2 %0, %1, %2;" : "=l"(r) : "l"(a), "l"(b)); return r;
}
__device__ __forceinline__ u64p mul2(u64p a, u64p b) {
    u64p r; asm("mul.rn.f32x2 %0, %1, %2;" : "=l"(r) : "l"(a), "l"(b)); return r;
}
__device__ __forceinline__ u64p fma2(u64p a, u64p b, u64p c) {
    u64p r; asm("fma.rn.f32x2 %0, %1, %2, %3;" : "=l"(r) : "l"(a), "l"(b), "l"(c)); return r;
}

#define PKC(v) ((((u64p)__float_as_uint(v)) << 32) | (u64p)__float_as_uint(v))

__global__ __launch_bounds__(THREADS, 7)
void orient_kernel(const float* __restrict__ x,
                   const float* __restrict__ gk,
                   float* __restrict__ out,
                   int B, float c_hi, float c_lo)
{
    __shared__ float s_gk[PS * PS];        // staged as 0.5 * gk
    __shared__ float s_priv[WPB][NB * NCOPY];
    __shared__ float s_hist[WPB][40];
    __shared__ float s_sm[WPB][40];

    const int tid   = threadIdx.x;
    const int w     = tid >> 5;
    const int lane  = tid & 31;
    const int patch = blockIdx.x * WPB + w;
    const bool valid = (patch < B);

    for (int i = tid; i < PS * PS; i += THREADS) s_gk[i] = 0.5f * gk[i];

    float* priv = s_priv[w];
    #pragma unroll
    for (int i = lane; i < NB * NCOPY; i += 32) priv[i] = 0.0f;
    __syncthreads();

    const float PI_F  = 3.14159265358979323846f;
    const float TPI_F = 6.28318530717958647692f;
    const unsigned FULL = 0xffffffffu;

    const u64p NEG12 = PKC(-1.0f);
    const u64p PI2   = PKC(PI_F);
    const u64p C362  = PKC(36.0f);
    const u64p EPS42 = PKC(4e-10f);          // 4 * 1e-10 (scale absorbed)
    const u64p ONE2  = PKC(1.0f);
    const u64p CHI2  = PKC(c_hi);
    const u64p CLO2  = PKC(c_lo);

    const int h    = lane >> 4;
    const int hl   = lane & 15;
    const int col0 = 2 * hl;

    const float* xp = x + (size_t)(valid ? patch : 0) * (PS * PS);
    const float* xh = xp + h * 16 * PS;
    const int gkb   = h * 16 * PS + col0;

    float2 cur = *(const float2*)(xh + col0);
    float2 prv = (h == 0) ? cur : *(const float2*)(xh - PS + col0);
    float2 nxt = *(const float2*)(xh + PS + col0);

    #pragma unroll
    for (int r = 0; r < 16; r++) {
        float Lup = __shfl_up_sync(FULL, cur.y, 1, 16);
        float Rdn = __shfl_down_sync(FULL, cur.x, 1, 16);
        float left0  = (hl == 0)  ? cur.x : Lup;
        float right1 = (hl == 15) ? cur.y : Rdn;

        // Unscaled gradients d = a - b (atan2f is bit-invariant to the exact
        // 0.5 power-of-two scale; magnitude absorbs it into gk and eps).
        u64p prv2 = pk(prv.x, prv.y);
        u64p nxt2 = pk(nxt.x, nxt.y);
        u64p dy2  = fma2(nxt2, NEG12, prv2);              // prv - nxt  (== 2*gy)
        u64p ga   = pk(left0, cur.x);
        u64p gb   = pk(cur.y, right1);
        u64p dx2  = fma2(gb, NEG12, ga);                  // left - right (== 2*gx)

        float dx0, dx1, dy0, dy1;
        upk(dx2, dx0, dx1);
        upk(dy2, dy0, dy1);

        // FROZEN: libdevice atan2f — bit-identical to atan2f(0.5dy, 0.5dx)
        float ori0 = atan2f(dy0, dx0);
        float ori1 = atan2f(dy1, dx1);

        // FROZEN chain: t = RN(36 * RN(ori+pi)); obig = RN(t / TPI_F) via
        // correctly-rounded multiply by double-float (c_hi, c_lo).
        u64p t36   = mul2(add2(pk(ori0, ori1), PI2), C362);
        u64p obig2 = fma2(t36, CHI2, mul2(t36, CLO2));
        float obig0, obig1; upk(obig2, obig0, obig1);
        float bo00 = floorf(obig0);
        float bo01 = floorf(obig1);
        int bx = (int)bo00; if (bx >= NB) bx -= NB;
        int by = (int)bo01; if (by >= NB) by -= NB;

        // continuous path: wo1, mag (= sqrt(dx^2+dy^2+4e-10) * 0.5*gk), wv
        u64p wo2  = fma2(pk(bo00, bo01), NEG12, obig2);   // obig - bo0
        u64p m2v  = fma2(dx2, dx2, fma2(dy2, dy2, EPS42));
        float m20, m21; upk(m2v, m20, m21);
        u64p rs2  = pk(rsqrtf(m20), rsqrtf(m21));
        u64p gk2  = *(const u64p*)(s_gk + gkb + r * PS);  // LDS.64 (0.5*gk)
        u64p mag2 = mul2(mul2(m2v, rs2), gk2);
        u64p wv2  = mul2(fma2(wo2, NEG12, ONE2), mag2);   // (1-wo1)*mag
        float wx, wy; upk(wv2, wx, wy);

        // proven hist: lanes<16 apply own + partner updates sequentially
        int   bx2 = __shfl_down_sync(FULL, bx, 16);
        int   by2 = __shfl_down_sync(FULL, by, 16);
        float wx2 = __shfl_down_sync(FULL, wx, 16);
        float wy2 = __shfl_down_sync(FULL, wy, 16);
        if (lane < 16) {
            priv[bx  * NCOPY + hl] += wx;
            priv[by  * NCOPY + hl] += wy;
            priv[bx2 * NCOPY + hl] += wx2;
            priv[by2 * NCOPY + hl] += wy2;
        }

        prv = cur;
        cur = nxt;
        if (r < 15) {
            if (r < 14 || h == 0) nxt = *(const float2*)(xh + (r + 2) * PS + col0);
            else                  nxt = cur;
        }
    }
    __syncwarp();

    // reduce 16 copies -> 36 bins (conflict-free rotation)
    const int rot = lane >> 1;
    float s1 = 0.0f;
    #pragma unroll
    for (int c = 0; c < NCOPY; c++) {
        int cc = (c + rot) & 15;
        s1 += priv[lane * NCOPY + cc];
    }
    const int l2 = 32 + (lane & 3);
    float s2 = 0.0f;
    #pragma unroll
    for (int c = 0; c < NCOPY; c++) {
        int cc = (c + rot) & 15;
        s2 += priv[l2 * NCOPY + cc];
    }
    s_hist[w][lane] = s1;
    if (lane < 4) s_hist[w][32 + lane] = s2;
    __syncwarp();

    // zero-padded smoothing [0.33, 0.34, 0.33]
    {
        float h0 = s_hist[w][lane];
        float hm = (lane > 0) ? s_hist[w][lane - 1] : 0.0f;
        float hp = s_hist[w][lane + 1];
        float a  = __fmul_rn(0.33f, hm);
        float bb = __fmul_rn(0.34f, h0);
        float c  = __fmul_rn(0.33f, hp);
        s_sm[w][lane] = __fadd_rn(__fadd_rn(a, bb), c);
    }
    if (lane < 4) {
        int i = 32 + lane;
        float h0 = s_hist[w][i];
        float hm = s_hist[w][i - 1];
        float hp = (i < NB - 1) ? s_hist[w][i + 1] : 0.0f;
        float a  = __fmul_rn(0.33f, hm);
        float bb = __fmul_rn(0.34f, h0);
        float c  = __fmul_rn(0.33f, hp);
        s_sm[w][i] = __fadd_rn(__fadd_rn(a, bb), c);
    }
    __syncwarp();

    if (lane == 0 && valid) {
        float best = s_sm[w][0];
        int   bi   = 0;
        #pragma unroll
        for (int i = 1; i < NB; i++) {
            float v = s_sm[w][i];
            if (v > best) { best = v; bi = i; }
        }
        float ang = __fsub_rn(__fdiv_rn(__fmul_rn(TPI_F, (float)bi), (float)NB), PI_F);
        out[patch] = -ang;
    }
}

extern "C" void kernel_launch(void* const* d_in, const int* in_sizes, int n_in,
                              void* d_out, int out_size)
{
    const float* x  = (const float*)d_in[0];
    const float* gk = (const float*)d_in[1];
    float* out = (float*)d_out;
    int B = in_sizes[0] / (PS * PS);
    int nblocks = (B + WPB - 1) / WPB;

    // double-float reciprocal of the fp32 2*pi constant (for correctly-rounded
    // division-by-constant inside the kernel)
    const float TPI_F = 6.28318530717958647692f;
    double inv = 1.0 / (double)TPI_F;
    float c_hi = (float)inv;
    float c_lo = (float)(inv - (double)c_hi);

    orient_kernel<<<nblocks, THREADS>>>(x, gk, out, B, c_hi, c_lo);
}

// round 9
// speedup vs baseline: 1.2320x; 1.0911x over previous
#include <cuda_runtime.h>
#include <math.h>

#define PS 32
#define NB 36
#define WPB 8
#define THREADS (WPB * 32)
#define NCOPY 32               // one private hist copy per lane: no shuffles, no races

typedef unsigned long long u64p;

__device__ __forceinline__ u64p pk(float lo, float hi) {
    u64p r; asm("mov.b64 %0, {%1, %2};" : "=l"(r) : "f"(lo), "f"(hi)); return r;
}
__device__ __forceinline__ void upk(u64p v, float& lo, float& hi) {
    asm("mov.b64 {%0, %1}, %2;" : "=f"(lo), "=f"(hi) : "l"(v));
}
__device__ __forceinline__ u64p add2(u64p a, u64p b) {
    u64p r; asm("add.rn.f32x2 %0, %1, %2;" : "=l"(r) : "l"(a), "l"(b)); return r;
}
__device__ __forceinline__ u64p mul2(u64p a, u64p b) {
    u64p r; asm("mul.rn.f32x2 %0, %1, %2;" : "=l"(r) : "l"(a), "l"(b)); return r;
}
__device__ __forceinline__ u64p fma2(u64p a, u64p b, u64p c) {
    u64p r; asm("fma.rn.f32x2 %0, %1, %2, %3;" : "=l"(r) : "l"(a), "l"(b), "l"(c)); return r;
}

#define PKC(v) ((((u64p)__float_as_uint(v)) << 32) | (u64p)__float_as_uint(v))

__global__ __launch_bounds__(THREADS, 5)
void orient_kernel(const float* __restrict__ x,
                   const float* __restrict__ gk,
                   float* __restrict__ out,
                   int B, float c_hi, float c_lo)
{
    __shared__ float s_gk[PS * PS];                       // staged as 0.5 * gk
    __shared__ __align__(8) float s_priv[WPB][NB * NCOPY];
    __shared__ float s_hist[WPB][40];
    __shared__ float s_sm[WPB][40];

    const int tid   = threadIdx.x;
    const int w     = tid >> 5;
    const int lane  = tid & 31;
    const int patch = blockIdx.x * WPB + w;
    const bool valid = (patch < B);

    for (int i = tid; i < PS * PS; i += THREADS) s_gk[i] = 0.5f * gk[i];

    float* priv = s_priv[w];
    {   // packed zeroing: NB*NCOPY floats = 576 u64 per warp, 18 per lane
        u64p* pz = (u64p*)priv;
        #pragma unroll
        for (int i = lane; i < (NB * NCOPY) / 2; i += 32) pz[i] = 0ull;
    }
    __syncthreads();

    const float PI_F  = 3.14159265358979323846f;
    const float TPI_F = 6.28318530717958647692f;
    const unsigned FULL = 0xffffffffu;

    const u64p NEG12 = PKC(-1.0f);
    const u64p PI2   = PKC(PI_F);
    const u64p C362  = PKC(36.0f);
    const u64p EPS42 = PKC(4e-10f);          // 4 * 1e-10 (grad scale absorbed)
    const u64p ONE2  = PKC(1.0f);
    const u64p CHI2  = PKC(c_hi);
    const u64p CLO2  = PKC(c_lo);

    const int h    = lane >> 4;              // row-half
    const int hl   = lane & 15;              // column-pair index
    const int col0 = 2 * hl;

    const float* xp = x + (size_t)(valid ? patch : 0) * (PS * PS);
    const float* xh = xp + h * 16 * PS;
    const int gkb   = h * 16 * PS + col0;

    float2 cur = *(const float2*)(xh + col0);
    float2 prv = (h == 0) ? cur : *(const float2*)(xh - PS + col0);
    float2 nxt = *(const float2*)(xh + PS + col0);

    #pragma unroll
    for (int r = 0; r < 16; r++) {
        float Lup = __shfl_up_sync(FULL, cur.y, 1, 16);
        float Rdn = __shfl_down_sync(FULL, cur.x, 1, 16);
        float left0  = (hl == 0)  ? cur.x : Lup;
        float right1 = (hl == 15) ? cur.y : Rdn;

        // Unscaled gradients (atan2f bit-invariant to exact 0.5 scaling)
        u64p prv2 = pk(prv.x, prv.y);
        u64p nxt2 = pk(nxt.x, nxt.y);
        u64p dy2  = fma2(nxt2, NEG12, prv2);              // prv - nxt
        u64p ga   = pk(left0, cur.x);
        u64p gb   = pk(cur.y, right1);
        u64p dx2  = fma2(gb, NEG12, ga);                  // left - right

        float dx0, dx1, dy0, dy1;
        upk(dx2, dx0, dx1);
        upk(dy2, dy0, dy1);

        // FROZEN: libdevice atan2f (bit-exact vs XLA)
        float ori0 = atan2f(dy0, dx0);
        float ori1 = atan2f(dy1, dx1);

        // FROZEN chain: t36 = RN(36*RN(ori+pi)); obig = RN(t36/TPI_F) via
        // correctly-rounded double-float multiply
        u64p t36   = mul2(add2(pk(ori0, ori1), PI2), C362);
        u64p obig2 = fma2(t36, CHI2, mul2(t36, CLO2));
        float obig0, obig1; upk(obig2, obig0, obig1);
        float bo00 = floorf(obig0);
        float bo01 = floorf(obig1);
        int bx = (int)bo00; if (bx >= NB) bx -= NB;
        int by = (int)bo01; if (by >= NB) by -= NB;

        // continuous path: wo1, mag, wv
        u64p wo2  = fma2(pk(bo00, bo01), NEG12, obig2);
        u64p m2v  = fma2(dx2, dx2, fma2(dy2, dy2, EPS42));
        float m20, m21; upk(m2v, m20, m21);
        u64p rs2  = pk(rsqrtf(m20), rsqrtf(m21));
        u64p gk2  = *(const u64p*)(s_gk + gkb + r * PS);
        u64p mag2 = mul2(mul2(m2v, rs2), gk2);
        u64p wv2  = mul2(fma2(wo2, NEG12, ONE2), mag2);
        float wx, wy; upk(wv2, wx, wy);

        // per-lane private hist: bank == lane always, no conflicts, no races
        priv[bx * NCOPY + lane] += wx;
        priv[by * NCOPY + lane] += wy;

        prv = cur;
        cur = nxt;
        if (r < 15) {
            if (r < 14 || h == 0) nxt = *(const float2*)(xh + (r + 2) * PS + col0);
            else                  nxt = cur;
        }
    }
    __syncwarp();

    // reduce 32 copies -> 36 bins with packed LDS.64 (2-way conflicts max)
    // loop1: bin = lane; copies paired (2c, 2c+1), rotated per lane
    u64p acc1 = 0ull;
    #pragma unroll
    for (int c = 0; c < 16; c++) {
        int cc0 = 2 * ((c + lane) & 15);
        acc1 = add2(acc1, *(const u64p*)(priv + lane * NCOPY + cc0));
    }
    float a1lo, a1hi; upk(acc1, a1lo, a1hi);
    float s1 = a1lo + a1hi;

    const int l2 = 32 + (lane & 3);
    u64p acc2 = 0ull;
    #pragma unroll
    for (int c = 0; c < 16; c++) {
        int cc0 = 2 * ((c + lane) & 15);
        acc2 = add2(acc2, *(const u64p*)(priv + l2 * NCOPY + cc0));
    }
    float a2lo, a2hi; upk(acc2, a2lo, a2hi);
    float s2 = a2lo + a2hi;

    s_hist[w][lane] = s1;
    if (lane < 4) s_hist[w][32 + lane] = s2;
    __syncwarp();

    // zero-padded smoothing [0.33, 0.34, 0.33]
    {
        float h0 = s_hist[w][lane];
        float hm = (lane > 0) ? s_hist[w][lane - 1] : 0.0f;
        float hp = s_hist[w][lane + 1];
        float a  = __fmul_rn(0.33f, hm);
        float bb = __fmul_rn(0.34f, h0);
        float c  = __fmul_rn(0.33f, hp);
        s_sm[w][lane] = __fadd_rn(__fadd_rn(a, bb), c);
    }
    if (lane < 4) {
        int i = 32 + lane;
        float h0 = s_hist[w][i];
        float hm = s_hist[w][i - 1];
        float hp = (i < NB - 1) ? s_hist[w][i + 1] : 0.0f;
        float a  = __fmul_rn(0.33f, hm);
        float bb = __fmul_rn(0.34f, h0);
        float c  = __fmul_rn(0.33f, hp);
        s_sm[w][i] = __fadd_rn(__fadd_rn(a, bb), c);
    }
    __syncwarp();

    if (lane == 0 && valid) {
        float best = s_sm[w][0];
        int   bi   = 0;
        #pragma unroll
        for (int i = 1; i < NB; i++) {
            float v = s_sm[w][i];
            if (v > best) { best = v; bi = i; }
        }
        float ang = __fsub_rn(__fdiv_rn(__fmul_rn(TPI_F, (float)bi), (float)NB), PI_F);
        out[patch] = -ang;
    }
}

extern "C" void kernel_launch(void* const* d_in, const int* in_sizes, int n_in,
                              void* d_out, int out_size)
{
    const float* x  = (const float*)d_in[0];
    const float* gk = (const float*)d_in[1];
    float* out = (float*)d_out;
    int B = in_sizes[0] / (PS * PS);
    int nblocks = (B + WPB - 1) / WPB;

    const float TPI_F = 6.28318530717958647692f;
    double inv = 1.0 / (double)TPI_F;
    float c_hi = (float)inv;
    float c_lo = (float)(inv - (double)c_hi);

    orient_kernel<<<nblocks, THREADS>>>(x, gk, out, B, c_hi, c_lo);
}